// round 2
// baseline (speedup 1.0000x reference)
#include <cuda_runtime.h>
#include <math.h>

// Problem constants
#define DM   768
#define BSZ  2
#define NSEQ 2048
#define NH   12
#define DK   64
#define ROWS (BSZ*NSEQ)          // 4096
#define SLOT ((size_t)ROWS*DM)   // 3,145,728 floats

typedef unsigned long long ull;

__device__ float g_scratch[10 * SLOT];

// ---------------- f32x2 packed helpers (Blackwell FFMA2 path) ----------------
__device__ __forceinline__ void ffma2(ull& d, ull a, ull b) {
    asm("fma.rn.f32x2 %0, %1, %2, %0;" : "+l"(d) : "l"(a), "l"(b));
}
__device__ __forceinline__ void fmul2(ull& d, ull a, ull b) {
    asm("mul.rn.f32x2 %0, %1, %2;" : "=l"(d) : "l"(a), "l"(b));
}
__device__ __forceinline__ ull pack2(float lo, float hi) {
    ull r;
    asm("mov.b64 %0, {%1, %2};" : "=l"(r) : "f"(lo), "f"(hi));
    return r;
}
__device__ __forceinline__ float p_lo(ull v) { return __uint_as_float((unsigned)v); }
__device__ __forceinline__ float p_hi(ull v) { return __uint_as_float((unsigned)(v >> 32)); }

// ---------------------------------------------------------------------------
// LayerNorm: one block per row; row < ROWS -> rgb w/ ln0, else ir w/ ln1
// ---------------------------------------------------------------------------
__global__ __launch_bounds__(256) void ln_kernel(
    const float* __restrict__ rgb, const float* __restrict__ ir,
    const float* __restrict__ w0, const float* __restrict__ b0,
    const float* __restrict__ w1, const float* __restrict__ b1,
    float* __restrict__ out_rgbn, float* __restrict__ out_irn)
{
    int row = blockIdx.x;
    const float* x; float* y; const float* w; const float* b;
    if (row < ROWS) { x = rgb + (size_t)row*DM; y = out_rgbn + (size_t)row*DM; w = w0; b = b0; }
    else { row -= ROWS; x = ir + (size_t)row*DM; y = out_irn + (size_t)row*DM; w = w1; b = b1; }

    int t = threadIdx.x;
    float v0 = x[t], v1 = x[t+256], v2 = x[t+512];
    float s  = v0+v1+v2;
    float sq = v0*v0 + v1*v1 + v2*v2;

    #pragma unroll
    for (int o = 16; o > 0; o >>= 1) {
        s  += __shfl_xor_sync(0xffffffffu, s,  o);
        sq += __shfl_xor_sync(0xffffffffu, sq, o);
    }
    __shared__ float shs[8], shq[8];
    int warp = t >> 5, lane = t & 31;
    if (lane == 0) { shs[warp] = s; shq[warp] = sq; }
    __syncthreads();
    float ts = 0.f, tq = 0.f;
    #pragma unroll
    for (int i = 0; i < 8; i++) { ts += shs[i]; tq += shq[i]; }

    const float inv = 1.0f / (float)DM;
    float mean = ts * inv;
    float var  = tq * inv - mean*mean;
    float rstd = rsqrtf(var + 1e-5f);

    y[t]     = (v0 - mean)*rstd*w[t]     + b[t];
    y[t+256] = (v1 - mean)*rstd*w[t+256] + b[t+256];
    y[t+512] = (v2 - mean)*rstd*w[t+512] + b[t+512];
}

// ---------------------------------------------------------------------------
// Batched GEMM + bias using packed f32x2 FMA.
// C[z] = A[z][4096,768] @ W[z][768,768] + bias[z]
// BM=128 BN=64 BK=16, 256 threads, thread tile 8 rows x 4 cols.
// Accumulators packed along row pairs; B staged DUPLICATED in smem so the
// broadcast operand is a natural packed load (no per-iteration movs).
// ---------------------------------------------------------------------------
#define BM 128
#define BN 64
#define BK 16

struct GemmBatch {
    const float* A[6];
    const float* W[6];
    const float* bias[6];
    float*       C[6];
};

__global__ __launch_bounds__(256) void gemm_bias2(GemmBatch gb)
{
    __shared__ float As[BK][BM];        // transposed A tile
    __shared__ float Bsd[BK][BN*2];     // duplicated B tile: col j at [2j],[2j+1]

    int z = blockIdx.z;
    const float* A    = gb.A[z];
    const float* W    = gb.W[z];
    const float* bias = gb.bias[z];
    float*       C    = gb.C[z];

    const int K  = DM;
    const int Nn = DM;

    int t  = threadIdx.x;
    int tx = t & 15;          // col group (4 cols)
    int ty = t >> 4;          // row group (8 rows)
    int bx = blockIdx.x;      // N tile
    int by = blockIdx.y;      // M tile

    int arow = t >> 2;
    int acol = (t & 3) * 4;
    int brow = t >> 4;
    int bcol = (t & 15) * 4;

    const float* Aptr = A + (size_t)(by*BM + arow)*K + acol;
    const float* Wptr = W + (size_t)brow*Nn + bx*BN + bcol;

    ull acc[4][4];
    #pragma unroll
    for (int i = 0; i < 4; i++)
        #pragma unroll
        for (int j = 0; j < 4; j++) acc[i][j] = 0ull;

    // initial prefetch
    float4 a0 = *(const float4*)(Aptr);
    float4 a1 = *(const float4*)(Aptr + (size_t)64*K);
    float4 bv = *(const float4*)(Wptr);

    for (int k0 = 0; k0 < K; k0 += BK) {
        // stage (smem free: either first iter or post-compute sync below)
        As[acol+0][arow]    = a0.x;
        As[acol+1][arow]    = a0.y;
        As[acol+2][arow]    = a0.z;
        As[acol+3][arow]    = a0.w;
        As[acol+0][arow+64] = a1.x;
        As[acol+1][arow+64] = a1.y;
        As[acol+2][arow+64] = a1.z;
        As[acol+3][arow+64] = a1.w;
        *(float4*)&Bsd[brow][bcol*2]     = make_float4(bv.x, bv.x, bv.y, bv.y);
        *(float4*)&Bsd[brow][bcol*2 + 4] = make_float4(bv.z, bv.z, bv.w, bv.w);
        __syncthreads();

        Aptr += BK;
        Wptr += (size_t)BK * Nn;
        if (k0 + BK < K) {
            a0 = *(const float4*)(Aptr);
            a1 = *(const float4*)(Aptr + (size_t)64*K);
            bv = *(const float4*)(Wptr);
        }

        #pragma unroll
        for (int kk = 0; kk < BK; kk++) {
            ulonglong2 ap01 = *(const ulonglong2*)&As[kk][ty*8];     // rows (0,1),(2,3)
            ulonglong2 ap23 = *(const ulonglong2*)&As[kk][ty*8+4];   // rows (4,5),(6,7)
            ulonglong2 bd01 = *(const ulonglong2*)&Bsd[kk][tx*8];    // (b0,b0),(b1,b1)
            ulonglong2 bd23 = *(const ulonglong2*)&Bsd[kk][tx*8+4];  // (b2,b2),(b3,b3)
            ull ap[4] = {ap01.x, ap01.y, ap23.x, ap23.y};
            ull bd[4] = {bd01.x, bd01.y, bd23.x, bd23.y};
            #pragma unroll
            for (int i = 0; i < 4; i++)
                #pragma unroll
                for (int j = 0; j < 4; j++)
                    ffma2(acc[i][j], ap[i], bd[j]);
        }
        __syncthreads();
    }

    int crow = by*BM + ty*8;
    int ccol = bx*BN + tx*4;
    float4 b4 = *(const float4*)(bias + ccol);
    #pragma unroll
    for (int r = 0; r < 8; r++) {
        int ip = r >> 1;
        float4 o;
        if ((r & 1) == 0) {
            o.x = p_lo(acc[ip][0]) + b4.x;
            o.y = p_lo(acc[ip][1]) + b4.y;
            o.z = p_lo(acc[ip][2]) + b4.z;
            o.w = p_lo(acc[ip][3]) + b4.w;
        } else {
            o.x = p_hi(acc[ip][0]) + b4.x;
            o.y = p_hi(acc[ip][1]) + b4.y;
            o.z = p_hi(acc[ip][2]) + b4.z;
            o.w = p_hi(acc[ip][3]) + b4.w;
        }
        *(float4*)(C + (size_t)(crow+r)*Nn + ccol) = o;
    }
}

// ---------------------------------------------------------------------------
// Flash attention with packed f32x2 FMA.
// grid (NSEQ/64, NH, 4): z = which*2 + b ; 64 threads, 1 query row per thread.
// QK packs along d (q reg pairs x K smem pairs, both natural).
// PV packs along d (p scalar dup, V smem pairs natural).
// ---------------------------------------------------------------------------
#define BR 64
#define BC 16
__global__ __launch_bounds__(64) void attn2(
    const float* __restrict__ qir,  const float* __restrict__ kvis, const float* __restrict__ vvis,
    const float* __restrict__ qvis, const float* __restrict__ kir,  const float* __restrict__ vir,
    float* __restrict__ att0, float* __restrict__ att1)
{
    __shared__ float Ks[BC][DK];
    __shared__ float Vs[BC][DK];

    int z = blockIdx.z;
    int which = z >> 1;
    int b = z & 1;
    const float *Qg, *Kg, *Vg; float* Og;
    if (which == 0) { Qg = qir;  Kg = kvis; Vg = vvis; Og = att0; }
    else            { Qg = qvis; Kg = kir;  Vg = vir;  Og = att1; }

    int t = threadIdx.x;
    int h = blockIdx.y;
    int qrow = blockIdx.x * BR + t;

    const size_t headoff = (size_t)h * DK;
    const float* qptr = Qg + ((size_t)(b*NSEQ) + qrow)*DM + headoff;

    const float scale = 0.125f;   // 1/sqrt(64)
    ull q2[32];                   // 32 packed pairs = 64 floats
    #pragma unroll
    for (int d4 = 0; d4 < DK/4; d4++) {
        float4 v = *(const float4*)(qptr + d4*4);
        q2[2*d4]   = pack2(v.x*scale, v.y*scale);
        q2[2*d4+1] = pack2(v.z*scale, v.w*scale);
    }

    float m = -INFINITY, l = 0.f;
    ull o2[32];
    #pragma unroll
    for (int u = 0; u < 32; u++) o2[u] = 0ull;

    for (int kt = 0; kt < NSEQ/BC; kt++) {
        // stage K,V tile (16 rows x 64 cols)
        #pragma unroll
        for (int i = 0; i < 4; i++) {
            int idx = t + i*64;       // 0..255
            int row = idx >> 4;
            int d4  = idx & 15;
            size_t goff = ((size_t)(b*NSEQ) + kt*BC + row)*DM + headoff;
            *(float4*)&Ks[row][d4*4] = *(const float4*)(Kg + goff + d4*4);
            *(float4*)&Vs[row][d4*4] = *(const float4*)(Vg + goff + d4*4);
        }
        __syncthreads();

        float s[BC];
        #pragma unroll
        for (int j = 0; j < BC; j++) {
            const ulonglong2* kp = (const ulonglong2*)Ks[j];
            ull accA = 0ull, accB = 0ull;
            #pragma unroll
            for (int u = 0; u < 16; u++) {
                ulonglong2 kv = kp[u];
                ffma2(accA, q2[2*u],   kv.x);
                ffma2(accB, q2[2*u+1], kv.y);
            }
            s[j] = (p_lo(accA) + p_hi(accA)) + (p_lo(accB) + p_hi(accB));
        }

        float m_new = m;
        #pragma unroll
        for (int j = 0; j < BC; j++) m_new = fmaxf(m_new, s[j]);
        float corr = __expf(m - m_new);
        float psum = 0.f;
        #pragma unroll
        for (int j = 0; j < BC; j++) { s[j] = __expf(s[j] - m_new); psum += s[j]; }
        l = l * corr + psum;

        ull corr2 = pack2(corr, corr);
        #pragma unroll
        for (int u = 0; u < 32; u++) fmul2(o2[u], o2[u], corr2);

        #pragma unroll
        for (int j = 0; j < BC; j++) {
            ull pj = pack2(s[j], s[j]);
            const ulonglong2* vp = (const ulonglong2*)Vs[j];
            #pragma unroll
            for (int u = 0; u < 16; u++) {
                ulonglong2 vv = vp[u];
                ffma2(o2[2*u],   pj, vv.x);
                ffma2(o2[2*u+1], pj, vv.y);
            }
        }
        m = m_new;
        __syncthreads();
    }

    float inv_l = 1.0f / l;
    float* optr = Og + ((size_t)(b*NSEQ) + qrow)*DM + headoff;
    #pragma unroll
    for (int d4 = 0; d4 < DK/4; d4++) {
        float4 v;
        v.x = p_lo(o2[2*d4])   * inv_l;
        v.y = p_hi(o2[2*d4])   * inv_l;
        v.z = p_lo(o2[2*d4+1]) * inv_l;
        v.w = p_hi(o2[2*d4+1]) * inv_l;
        *(float4*)(optr + d4*4) = v;
    }
}

// ---------------------------------------------------------------------------
// Launch
// ---------------------------------------------------------------------------
extern "C" void kernel_launch(void* const* d_in, const int* in_sizes, int n_in,
                              void* d_out, int out_size)
{
    const float* rgb    = (const float*)d_in[0];
    const float* ir     = (const float*)d_in[1];
    const float* ln0_w  = (const float*)d_in[2];
    const float* ln0_b  = (const float*)d_in[3];
    const float* ln1_w  = (const float*)d_in[4];
    const float* ln1_b  = (const float*)d_in[5];
    const float* Wq_vis = (const float*)d_in[6];
    const float* bq_vis = (const float*)d_in[7];
    const float* Wk_vis = (const float*)d_in[8];
    const float* bk_vis = (const float*)d_in[9];
    const float* Wq_ir  = (const float*)d_in[10];
    const float* bq_ir  = (const float*)d_in[11];
    const float* Wk_ir  = (const float*)d_in[12];
    const float* bk_ir  = (const float*)d_in[13];
    const float* Wv_vis = (const float*)d_in[14];
    const float* bv_vis = (const float*)d_in[15];
    const float* Wv_ir  = (const float*)d_in[16];
    const float* bv_ir  = (const float*)d_in[17];
    const float* Wo_vis = (const float*)d_in[18];
    const float* bo_vis = (const float*)d_in[19];
    const float* Wo_ir  = (const float*)d_in[20];
    const float* bo_ir  = (const float*)d_in[21];
    float* out = (float*)d_out;

    float* scr = nullptr;
    cudaGetSymbolAddress((void**)&scr, g_scratch);
    float* rgbn = scr + 0*SLOT;
    float* irn  = scr + 1*SLOT;
    float* qvis = scr + 2*SLOT;
    float* kvis = scr + 3*SLOT;
    float* vvis = scr + 4*SLOT;
    float* qir  = scr + 5*SLOT;
    float* kir  = scr + 6*SLOT;
    float* vir  = scr + 7*SLOT;
    float* att0 = scr + 8*SLOT;
    float* att1 = scr + 9*SLOT;

    // 1. LayerNorms
    ln_kernel<<<2*ROWS, 256>>>(rgb, ir, ln0_w, ln0_b, ln1_w, ln1_b, rgbn, irn);

    // 2. All six projections in ONE batched launch
    GemmBatch proj;
    proj.A[0]=rgbn; proj.W[0]=Wq_vis; proj.bias[0]=bq_vis; proj.C[0]=qvis;
    proj.A[1]=rgbn; proj.W[1]=Wk_vis; proj.bias[1]=bk_vis; proj.C[1]=kvis;
    proj.A[2]=rgbn; proj.W[2]=Wv_vis; proj.bias[2]=bv_vis; proj.C[2]=vvis;
    proj.A[3]=irn;  proj.W[3]=Wq_ir;  proj.bias[3]=bq_ir;  proj.C[3]=qir;
    proj.A[4]=irn;  proj.W[4]=Wk_ir;  proj.bias[4]=bk_ir;  proj.C[4]=kir;
    proj.A[5]=irn;  proj.W[5]=Wv_ir;  proj.bias[5]=bv_ir;  proj.C[5]=vir;
    dim3 pgrid(DM/BN, ROWS/BM, 6);   // (12, 32, 6)
    gemm_bias2<<<pgrid, 256>>>(proj);

    // 3. Both cross-attentions in one launch
    dim3 agrid(NSEQ/BR, NH, 4);      // (32, 12, 4)
    attn2<<<agrid, BR>>>(qir, kvis, vvis, qvis, kir, vir, att0, att1);

    // 4. Output projections (batched, straight into d_out)
    GemmBatch op;
    op.A[0]=att0; op.W[0]=Wo_vis; op.bias[0]=bo_vis; op.C[0]=out;
    op.A[1]=att1; op.W[1]=Wo_ir;  op.bias[1]=bo_ir;  op.C[1]=out + SLOT;
    for (int i = 2; i < 6; i++) { op.A[i]=att0; op.W[i]=Wo_vis; op.bias[i]=bo_vis; op.C[i]=out; }
    dim3 ogrid(DM/BN, ROWS/BM, 2);   // (12, 32, 2)
    gemm_bias2<<<ogrid, 256>>>(op);
}

// round 3
// speedup vs baseline: 1.6470x; 1.6470x over previous
#include <cuda_runtime.h>
#include <math.h>

// Problem constants
#define DM   768
#define BSZ  2
#define NSEQ 2048
#define NH   12
#define DK   64
#define ROWS (BSZ*NSEQ)          // 4096
#define SLOT ((size_t)ROWS*DM)   // 3,145,728 floats

__device__ float g_scratch[10 * SLOT];

// ---------------------------------------------------------------------------
// LayerNorm: one block per row; row < ROWS -> rgb w/ ln0, else ir w/ ln1
// ---------------------------------------------------------------------------
__global__ __launch_bounds__(256) void ln_kernel(
    const float* __restrict__ rgb, const float* __restrict__ ir,
    const float* __restrict__ w0, const float* __restrict__ b0,
    const float* __restrict__ w1, const float* __restrict__ b1,
    float* __restrict__ out_rgbn, float* __restrict__ out_irn)
{
    int row = blockIdx.x;
    const float* x; float* y; const float* w; const float* b;
    if (row < ROWS) { x = rgb + (size_t)row*DM; y = out_rgbn + (size_t)row*DM; w = w0; b = b0; }
    else { row -= ROWS; x = ir + (size_t)row*DM; y = out_irn + (size_t)row*DM; w = w1; b = b1; }

    int t = threadIdx.x;
    float v0 = x[t], v1 = x[t+256], v2 = x[t+512];
    float s  = v0+v1+v2;
    float sq = v0*v0 + v1*v1 + v2*v2;

    #pragma unroll
    for (int o = 16; o > 0; o >>= 1) {
        s  += __shfl_xor_sync(0xffffffffu, s,  o);
        sq += __shfl_xor_sync(0xffffffffu, sq, o);
    }
    __shared__ float shs[8], shq[8];
    int warp = t >> 5, lane = t & 31;
    if (lane == 0) { shs[warp] = s; shq[warp] = sq; }
    __syncthreads();
    float ts = 0.f, tq = 0.f;
    #pragma unroll
    for (int i = 0; i < 8; i++) { ts += shs[i]; tq += shq[i]; }

    const float inv = 1.0f / (float)DM;
    float mean = ts * inv;
    float var  = tq * inv - mean*mean;
    float rstd = rsqrtf(var + 1e-5f);

    y[t]     = (v0 - mean)*rstd*w[t]     + b[t];
    y[t+256] = (v1 - mean)*rstd*w[t+256] + b[t+256];
    y[t+512] = (v2 - mean)*rstd*w[t+512] + b[t+512];
}

// ---------------------------------------------------------------------------
// Batched scalar GEMM + bias.  C[z] = A[z][4096,768] @ W[z][768,768] + bias[z]
// BM=128 BN=128 BK=8, 256 threads, 8x8 register tile per thread.
// 4 LDS.128 per 64 FFMA in the inner loop.
// ---------------------------------------------------------------------------
#define BM 128
#define BN 128
#define BK 8

struct GemmBatch {
    const float* A[6];
    const float* W[6];
    const float* bias[6];
    float*       C[6];
};

__global__ __launch_bounds__(256) void gemm_bias(GemmBatch gb)
{
    __shared__ float As[BK][BM];   // transposed A tile
    __shared__ float Bs[BK][BN];

    int z = blockIdx.z;
    const float* A    = gb.A[z];
    const float* W    = gb.W[z];
    const float* bias = gb.bias[z];
    float*       C    = gb.C[z];

    int t  = threadIdx.x;
    int tx = t & 15;               // col group  (8 cols)
    int ty = t >> 4;               // row group  (8 rows)
    int bx = blockIdx.x;           // N tile
    int by = blockIdx.y;           // M tile

    int arow = t >> 1;             // 0..127
    int acol = (t & 1) * 4;        // 0 or 4
    int brow = t >> 5;             // 0..7
    int bcol = (t & 31) * 4;       // 0..124

    const float* Aptr = A + (size_t)(by*BM + arow)*DM + acol;
    const float* Wptr = W + (size_t)brow*DM + bx*BN + bcol;

    float acc[8][8];
    #pragma unroll
    for (int i = 0; i < 8; i++)
        #pragma unroll
        for (int j = 0; j < 8; j++) acc[i][j] = 0.f;

    float4 a4 = *(const float4*)(Aptr);
    float4 b4 = *(const float4*)(Wptr);

    for (int k0 = 0; k0 < DM; k0 += BK) {
        As[acol+0][arow] = a4.x;
        As[acol+1][arow] = a4.y;
        As[acol+2][arow] = a4.z;
        As[acol+3][arow] = a4.w;
        *(float4*)&Bs[brow][bcol] = b4;
        __syncthreads();

        Aptr += BK;
        Wptr += (size_t)BK * DM;
        if (k0 + BK < DM) {
            a4 = *(const float4*)(Aptr);
            b4 = *(const float4*)(Wptr);
        }

        #pragma unroll
        for (int kk = 0; kk < BK; kk++) {
            float4 x0 = *(const float4*)&As[kk][ty*8];
            float4 x1 = *(const float4*)&As[kk][ty*8+4];
            float4 y0 = *(const float4*)&Bs[kk][tx*8];
            float4 y1 = *(const float4*)&Bs[kk][tx*8+4];
            float xr[8] = {x0.x,x0.y,x0.z,x0.w,x1.x,x1.y,x1.z,x1.w};
            float yr[8] = {y0.x,y0.y,y0.z,y0.w,y1.x,y1.y,y1.z,y1.w};
            #pragma unroll
            for (int i = 0; i < 8; i++)
                #pragma unroll
                for (int j = 0; j < 8; j++)
                    acc[i][j] = fmaf(xr[i], yr[j], acc[i][j]);
        }
        __syncthreads();
    }

    int crow = by*BM + ty*8;
    int ccol = bx*BN + tx*8;
    float4 bb0 = *(const float4*)(bias + ccol);
    float4 bb1 = *(const float4*)(bias + ccol + 4);
    #pragma unroll
    for (int i = 0; i < 8; i++) {
        float4 o0, o1;
        o0.x = acc[i][0] + bb0.x;  o0.y = acc[i][1] + bb0.y;
        o0.z = acc[i][2] + bb0.z;  o0.w = acc[i][3] + bb0.w;
        o1.x = acc[i][4] + bb1.x;  o1.y = acc[i][5] + bb1.y;
        o1.z = acc[i][6] + bb1.z;  o1.w = acc[i][7] + bb1.w;
        float* cp = C + (size_t)(crow+i)*DM + ccol;
        *(float4*)(cp)     = o0;
        *(float4*)(cp + 4) = o1;
    }
}

// ---------------------------------------------------------------------------
// Flash attention, GEMM-style tiling.
// grid (NSEQ/64, NH, 4): z = which*2 + b ; 256 threads.
// Br=64 query rows, Bc=64 key rows per tile, thread tile 4x4 for S and O.
// Smem: Qt (Q transposed, x scale), KtPs (K transposed during S, reused as
// P row-major during PV), Vs (row-major). 48KB total.
// Softmax reductions via 16-lane shfl (row group = half warp).
// ---------------------------------------------------------------------------
#define ABR 64
#define ABC 64
__global__ __launch_bounds__(256) void attn3(
    const float* __restrict__ qir,  const float* __restrict__ kvis, const float* __restrict__ vvis,
    const float* __restrict__ qvis, const float* __restrict__ kir,  const float* __restrict__ vir,
    float* __restrict__ att0, float* __restrict__ att1)
{
    __shared__ float Qt[DK][ABR];     // [d][i]  16KB
    __shared__ float KtPs[DK][ABC];   // Kt: [d][j] during S ; Ps: [i][j] during PV
    __shared__ float Vs[ABC][DK];     // [j][d]  16KB

    int z = blockIdx.z;
    int which = z >> 1;
    int b = z & 1;
    const float *Qg, *Kg, *Vg; float* Og;
    if (which == 0) { Qg = qir;  Kg = kvis; Vg = vvis; Og = att0; }
    else            { Qg = qvis; Kg = kir;  Vg = vir;  Og = att1; }

    int t  = threadIdx.x;
    int tx = t & 15;               // col group (4 cols of S / 4 d of O)
    int ty = t >> 4;               // row group (4 rows)
    int h  = blockIdx.y;
    int qblk = blockIdx.x;

    const size_t headoff = (size_t)h * DK;
    const size_t batoff  = (size_t)b * NSEQ;

    // ---- stage Q transposed, pre-scaled ----
    {
        int row  = t >> 2;             // 0..63 (query row within tile)
        int dcol = (t & 3) * 16;       // 0,16,32,48
        const float* qbase = Qg + (batoff + qblk*ABR + row)*DM + headoff + dcol;
        const float scale = 0.125f;    // 1/sqrt(64)
        #pragma unroll
        for (int i = 0; i < 4; i++) {
            float4 v = *(const float4*)(qbase + i*4);
            Qt[dcol+i*4+0][row] = v.x*scale;
            Qt[dcol+i*4+1][row] = v.y*scale;
            Qt[dcol+i*4+2][row] = v.z*scale;
            Qt[dcol+i*4+3][row] = v.w*scale;
        }
    }

    float m[4], l[4], o[4][4];
    #pragma unroll
    for (int i = 0; i < 4; i++) {
        m[i] = -INFINITY; l[i] = 0.f;
        #pragma unroll
        for (int j = 0; j < 4; j++) o[i][j] = 0.f;
    }

    int jrow = t >> 2;             // 0..63 (key row within tile)
    int jcol = (t & 3) * 16;       // 0,16,32,48

    for (int kt = 0; kt < NSEQ/ABC; kt++) {
        // ---- stage K transposed and V row-major ----
        {
            const float* kbase = Kg + (batoff + kt*ABC + jrow)*DM + headoff + jcol;
            const float* vbase = Vg + (batoff + kt*ABC + jrow)*DM + headoff + jcol;
            #pragma unroll
            for (int i = 0; i < 4; i++) {
                float4 kv = *(const float4*)(kbase + i*4);
                KtPs[jcol+i*4+0][jrow] = kv.x;
                KtPs[jcol+i*4+1][jrow] = kv.y;
                KtPs[jcol+i*4+2][jrow] = kv.z;
                KtPs[jcol+i*4+3][jrow] = kv.w;
                float4 vv = *(const float4*)(vbase + i*4);
                *(float4*)&Vs[jrow][jcol+i*4] = vv;
            }
        }
        __syncthreads();

        // ---- S = Q @ K^T  (4x4 per thread) ----
        float s[4][4];
        #pragma unroll
        for (int i = 0; i < 4; i++)
            #pragma unroll
            for (int j = 0; j < 4; j++) s[i][j] = 0.f;

        #pragma unroll 8
        for (int d = 0; d < DK; d++) {
            float4 qa = *(const float4*)&Qt[d][ty*4];
            float4 kb = *(const float4*)&KtPs[d][tx*4];
            float qr[4] = {qa.x, qa.y, qa.z, qa.w};
            float kr[4] = {kb.x, kb.y, kb.z, kb.w};
            #pragma unroll
            for (int i = 0; i < 4; i++)
                #pragma unroll
                for (int j = 0; j < 4; j++)
                    s[i][j] = fmaf(qr[i], kr[j], s[i][j]);
        }

        // ---- online softmax (row groups = 16 consecutive lanes) ----
        #pragma unroll
        for (int i = 0; i < 4; i++) {
            float mx = fmaxf(fmaxf(s[i][0], s[i][1]), fmaxf(s[i][2], s[i][3]));
            #pragma unroll
            for (int off = 1; off < 16; off <<= 1)
                mx = fmaxf(mx, __shfl_xor_sync(0xffffffffu, mx, off));
            float mn = fmaxf(m[i], mx);
            float corr = __expf(m[i] - mn);
            m[i] = mn;
            float ps = 0.f;
            #pragma unroll
            for (int j = 0; j < 4; j++) {
                s[i][j] = __expf(s[i][j] - mn);
                ps += s[i][j];
            }
            #pragma unroll
            for (int off = 1; off < 16; off <<= 1)
                ps += __shfl_xor_sync(0xffffffffu, ps, off);
            l[i] = l[i]*corr + ps;
            #pragma unroll
            for (int j = 0; j < 4; j++) o[i][j] *= corr;
        }

        __syncthreads();   // everyone done reading Kt before P overwrite

        // ---- write P (row-major) into the Kt buffer ----
        #pragma unroll
        for (int i = 0; i < 4; i++)
            *(float4*)&KtPs[ty*4+i][tx*4] = make_float4(s[i][0], s[i][1], s[i][2], s[i][3]);

        __syncthreads();   // P visible

        // ---- O += P @ V  (4x4 per thread, j in chunks of 4) ----
        #pragma unroll 4
        for (int j0 = 0; j0 < ABC; j0 += 4) {
            float4 p0 = *(const float4*)&KtPs[ty*4+0][j0];
            float4 p1 = *(const float4*)&KtPs[ty*4+1][j0];
            float4 p2 = *(const float4*)&KtPs[ty*4+2][j0];
            float4 p3 = *(const float4*)&KtPs[ty*4+3][j0];
            float4 v0 = *(const float4*)&Vs[j0+0][tx*4];
            float4 v1 = *(const float4*)&Vs[j0+1][tx*4];
            float4 v2 = *(const float4*)&Vs[j0+2][tx*4];
            float4 v3 = *(const float4*)&Vs[j0+3][tx*4];
            float pr[4][4] = {{p0.x,p0.y,p0.z,p0.w},{p1.x,p1.y,p1.z,p1.w},
                              {p2.x,p2.y,p2.z,p2.w},{p3.x,p3.y,p3.z,p3.w}};
            float vr[4][4] = {{v0.x,v0.y,v0.z,v0.w},{v1.x,v1.y,v1.z,v1.w},
                              {v2.x,v2.y,v2.z,v2.w},{v3.x,v3.y,v3.z,v3.w}};
            #pragma unroll
            for (int i = 0; i < 4; i++)
                #pragma unroll
                for (int jj = 0; jj < 4; jj++) {
                    float p = pr[i][jj];
                    o[i][0] = fmaf(p, vr[jj][0], o[i][0]);
                    o[i][1] = fmaf(p, vr[jj][1], o[i][1]);
                    o[i][2] = fmaf(p, vr[jj][2], o[i][2]);
                    o[i][3] = fmaf(p, vr[jj][3], o[i][3]);
                }
        }

        __syncthreads();   // PV done before next tile overwrites Kt/Vs/P
    }

    // ---- epilogue ----
    #pragma unroll
    for (int i = 0; i < 4; i++) {
        float inv = 1.0f / l[i];
        float4 ov = make_float4(o[i][0]*inv, o[i][1]*inv, o[i][2]*inv, o[i][3]*inv);
        float* op = Og + (batoff + qblk*ABR + ty*4 + i)*DM + headoff + tx*4;
        *(float4*)op = ov;
    }
}

// ---------------------------------------------------------------------------
// Launch
// ---------------------------------------------------------------------------
extern "C" void kernel_launch(void* const* d_in, const int* in_sizes, int n_in,
                              void* d_out, int out_size)
{
    const float* rgb    = (const float*)d_in[0];
    const float* ir     = (const float*)d_in[1];
    const float* ln0_w  = (const float*)d_in[2];
    const float* ln0_b  = (const float*)d_in[3];
    const float* ln1_w  = (const float*)d_in[4];
    const float* ln1_b  = (const float*)d_in[5];
    const float* Wq_vis = (const float*)d_in[6];
    const float* bq_vis = (const float*)d_in[7];
    const float* Wk_vis = (const float*)d_in[8];
    const float* bk_vis = (const float*)d_in[9];
    const float* Wq_ir  = (const float*)d_in[10];
    const float* bq_ir  = (const float*)d_in[11];
    const float* Wk_ir  = (const float*)d_in[12];
    const float* bk_ir  = (const float*)d_in[13];
    const float* Wv_vis = (const float*)d_in[14];
    const float* bv_vis = (const float*)d_in[15];
    const float* Wv_ir  = (const float*)d_in[16];
    const float* bv_ir  = (const float*)d_in[17];
    const float* Wo_vis = (const float*)d_in[18];
    const float* bo_vis = (const float*)d_in[19];
    const float* Wo_ir  = (const float*)d_in[20];
    const float* bo_ir  = (const float*)d_in[21];
    float* out = (float*)d_out;

    float* scr = nullptr;
    cudaGetSymbolAddress((void**)&scr, g_scratch);
    float* rgbn = scr + 0*SLOT;
    float* irn  = scr + 1*SLOT;
    float* qvis = scr + 2*SLOT;
    float* kvis = scr + 3*SLOT;
    float* vvis = scr + 4*SLOT;
    float* qir  = scr + 5*SLOT;
    float* kir  = scr + 6*SLOT;
    float* vir  = scr + 7*SLOT;
    float* att0 = scr + 8*SLOT;
    float* att1 = scr + 9*SLOT;

    // 1. LayerNorms
    ln_kernel<<<2*ROWS, 256>>>(rgb, ir, ln0_w, ln0_b, ln1_w, ln1_b, rgbn, irn);

    // 2. All six projections in one batched launch
    GemmBatch proj;
    proj.A[0]=rgbn; proj.W[0]=Wq_vis; proj.bias[0]=bq_vis; proj.C[0]=qvis;
    proj.A[1]=rgbn; proj.W[1]=Wk_vis; proj.bias[1]=bk_vis; proj.C[1]=kvis;
    proj.A[2]=rgbn; proj.W[2]=Wv_vis; proj.bias[2]=bv_vis; proj.C[2]=vvis;
    proj.A[3]=irn;  proj.W[3]=Wq_ir;  proj.bias[3]=bq_ir;  proj.C[3]=qir;
    proj.A[4]=irn;  proj.W[4]=Wk_ir;  proj.bias[4]=bk_ir;  proj.C[4]=kir;
    proj.A[5]=irn;  proj.W[5]=Wv_ir;  proj.bias[5]=bv_ir;  proj.C[5]=vir;
    dim3 pgrid(DM/BN, ROWS/BM, 6);   // (6, 32, 6)
    gemm_bias<<<pgrid, 256>>>(proj);

    // 3. Both cross-attentions in one launch
    dim3 agrid(NSEQ/ABR, NH, 4);     // (32, 12, 4)
    attn3<<<agrid, 256>>>(qir, kvis, vvis, qvis, kir, vir, att0, att1);

    // 4. Output projections straight into d_out (out_vis then out_ir)
    GemmBatch op;
    op.A[0]=att0; op.W[0]=Wo_vis; op.bias[0]=bo_vis; op.C[0]=out;
    op.A[1]=att1; op.W[1]=Wo_ir;  op.bias[1]=bo_ir;  op.C[1]=out + SLOT;
    for (int i = 2; i < 6; i++) { op.A[i]=att0; op.W[i]=Wo_vis; op.bias[i]=bo_vis; op.C[i]=out; }
    dim3 ogrid(DM/BN, ROWS/BM, 2);   // (6, 32, 2)
    gemm_bias<<<ogrid, 256>>>(op);
}

// round 4
// speedup vs baseline: 3.8296x; 2.3251x over previous
#include <cuda_runtime.h>
#include <math.h>

// Problem constants
#define DM   768
#define BSZ  2
#define NSEQ 2048
#define NH   12
#define DK   64
#define ROWS (BSZ*NSEQ)          // 4096
#define SLOT ((size_t)ROWS*DM)   // 3,145,728 floats

__device__ float g_scratch[10 * SLOT];

// ---------------- TF32 mma helpers ----------------
__device__ __forceinline__ unsigned f2tf(float f) {
    unsigned u;
    asm("cvt.rna.tf32.f32 %0, %1;" : "=r"(u) : "f"(f));
    return u;
}
__device__ __forceinline__ void mma_tf32(
    float& c0, float& c1, float& c2, float& c3,
    unsigned a0, unsigned a1, unsigned a2, unsigned a3,
    unsigned b0, unsigned b1)
{
    asm("mma.sync.aligned.m16n8k8.row.col.f32.tf32.tf32.f32 "
        "{%0,%1,%2,%3},{%4,%5,%6,%7},{%8,%9},{%0,%1,%2,%3};"
        : "+f"(c0), "+f"(c1), "+f"(c2), "+f"(c3)
        : "r"(a0), "r"(a1), "r"(a2), "r"(a3), "r"(b0), "r"(b1));
}

// ---------------------------------------------------------------------------
// LayerNorm: one block per row; row < ROWS -> rgb w/ ln0, else ir w/ ln1
// ---------------------------------------------------------------------------
__global__ __launch_bounds__(256) void ln_kernel(
    const float* __restrict__ rgb, const float* __restrict__ ir,
    const float* __restrict__ w0, const float* __restrict__ b0,
    const float* __restrict__ w1, const float* __restrict__ b1,
    float* __restrict__ out_rgbn, float* __restrict__ out_irn)
{
    int row = blockIdx.x;
    const float* x; float* y; const float* w; const float* b;
    if (row < ROWS) { x = rgb + (size_t)row*DM; y = out_rgbn + (size_t)row*DM; w = w0; b = b0; }
    else { row -= ROWS; x = ir + (size_t)row*DM; y = out_irn + (size_t)row*DM; w = w1; b = b1; }

    int t = threadIdx.x;
    float v0 = x[t], v1 = x[t+256], v2 = x[t+512];
    float s  = v0+v1+v2;
    float sq = v0*v0 + v1*v1 + v2*v2;

    #pragma unroll
    for (int o = 16; o > 0; o >>= 1) {
        s  += __shfl_xor_sync(0xffffffffu, s,  o);
        sq += __shfl_xor_sync(0xffffffffu, sq, o);
    }
    __shared__ float shs[8], shq[8];
    int warp = t >> 5, lane = t & 31;
    if (lane == 0) { shs[warp] = s; shq[warp] = sq; }
    __syncthreads();
    float ts = 0.f, tq = 0.f;
    #pragma unroll
    for (int i = 0; i < 8; i++) { ts += shs[i]; tq += shq[i]; }

    const float inv = 1.0f / (float)DM;
    float mean = ts * inv;
    float var  = tq * inv - mean*mean;
    float rstd = rsqrtf(var + 1e-5f);

    y[t]     = (v0 - mean)*rstd*w[t]     + b[t];
    y[t+256] = (v1 - mean)*rstd*w[t+256] + b[t+256];
    y[t+512] = (v2 - mean)*rstd*w[t+512] + b[t+512];
}

// ---------------------------------------------------------------------------
// Batched TF32 tensor-core GEMM + bias.
// C[z] = A[z][4096,768] @ W[z][768,768] + bias[z]
// BM=128 BN=128 BK=16, 256 threads = 8 warps (2m x 4n), warp tile 64x32.
// mma.sync m16n8k8 tf32. Smem layouts [m][k]/[n][k] with pad 4 ->
// conflict-free fragment loads (bank = (20*row + k) % 32 covers all 32).
// ---------------------------------------------------------------------------
#define BM 128
#define BN 128
#define BK 16

struct GemmBatch {
    const float* A[6];
    const float* W[6];
    const float* bias[6];
    float*       C[6];
};

__global__ __launch_bounds__(256) void gemm_tf32(GemmBatch gb)
{
    __shared__ unsigned As[BM][BK+4];   // [m][k]
    __shared__ unsigned Bs[BN][BK+4];   // [n][k] (transposed during staging)

    int z = blockIdx.z;
    const float* A    = gb.A[z];
    const float* W    = gb.W[z];
    const float* bias = gb.bias[z];
    float*       C    = gb.C[z];

    int t    = threadIdx.x;
    int warp = t >> 5, lane = t & 31;
    int g    = lane >> 2;     // groupID 0..7
    int q4   = lane & 3;      // threadID_in_group 0..3
    int wm   = warp & 1;      // 2 m-warps  (64 rows each)
    int wn   = warp >> 1;     // 4 n-warps  (32 cols each)
    int bx   = blockIdx.x, by = blockIdx.y;

    // A staging: granule idx t -> row=t>>2 (0..63), kq=(t&3)*4 ; +256 -> row+64
    int s_arow = t >> 2;
    int s_akq  = (t & 3) * 4;
    // B staging: k = t&15, ngran = t>>4 (0..15) -> n4 = ngran*4 ; +256 -> n4+64
    int s_bk   = t & 15;
    int s_bn4  = (t >> 4) * 4;

    const float* Aptr0 = A + (size_t)(by*BM + s_arow)      * DM + s_akq;
    const float* Aptr1 = A + (size_t)(by*BM + s_arow + 64) * DM + s_akq;
    const float* Wptr  = W + (size_t)s_bk * DM + bx*BN + s_bn4;

    float acc[4][4][4];
    #pragma unroll
    for (int mt = 0; mt < 4; mt++)
        #pragma unroll
        for (int nt = 0; nt < 4; nt++)
            #pragma unroll
            for (int c = 0; c < 4; c++) acc[mt][nt][c] = 0.f;

    float4 pa0 = *(const float4*)(Aptr0);
    float4 pa1 = *(const float4*)(Aptr1);
    float4 pb0 = *(const float4*)(Wptr);
    float4 pb1 = *(const float4*)(Wptr + 64);

    for (int k0 = 0; k0 < DM; k0 += BK) {
        *(uint4*)&As[s_arow][s_akq] =
            make_uint4(f2tf(pa0.x), f2tf(pa0.y), f2tf(pa0.z), f2tf(pa0.w));
        *(uint4*)&As[s_arow+64][s_akq] =
            make_uint4(f2tf(pa1.x), f2tf(pa1.y), f2tf(pa1.z), f2tf(pa1.w));
        Bs[s_bn4+0][s_bk] = f2tf(pb0.x);
        Bs[s_bn4+1][s_bk] = f2tf(pb0.y);
        Bs[s_bn4+2][s_bk] = f2tf(pb0.z);
        Bs[s_bn4+3][s_bk] = f2tf(pb0.w);
        Bs[s_bn4+64][s_bk] = f2tf(pb1.x);
        Bs[s_bn4+65][s_bk] = f2tf(pb1.y);
        Bs[s_bn4+66][s_bk] = f2tf(pb1.z);
        Bs[s_bn4+67][s_bk] = f2tf(pb1.w);
        __syncthreads();

        Aptr0 += BK; Aptr1 += BK;
        Wptr  += (size_t)BK * DM;
        if (k0 + BK < DM) {
            pa0 = *(const float4*)(Aptr0);
            pa1 = *(const float4*)(Aptr1);
            pb0 = *(const float4*)(Wptr);
            pb1 = *(const float4*)(Wptr + 64);
        }

        #pragma unroll
        for (int kk = 0; kk < 2; kk++) {
            int kc = kk*8 + q4;
            unsigned af[4][4], bf[4][2];
            #pragma unroll
            for (int mt = 0; mt < 4; mt++) {
                int mr = wm*64 + mt*16 + g;
                af[mt][0] = As[mr][kc];
                af[mt][1] = As[mr+8][kc];
                af[mt][2] = As[mr][kc+4];
                af[mt][3] = As[mr+8][kc+4];
            }
            #pragma unroll
            for (int nt = 0; nt < 4; nt++) {
                int nc = wn*32 + nt*8 + g;
                bf[nt][0] = Bs[nc][kc];
                bf[nt][1] = Bs[nc][kc+4];
            }
            #pragma unroll
            for (int mt = 0; mt < 4; mt++)
                #pragma unroll
                for (int nt = 0; nt < 4; nt++)
                    mma_tf32(acc[mt][nt][0], acc[mt][nt][1], acc[mt][nt][2], acc[mt][nt][3],
                             af[mt][0], af[mt][1], af[mt][2], af[mt][3],
                             bf[nt][0], bf[nt][1]);
        }
        __syncthreads();
    }

    #pragma unroll
    for (int mt = 0; mt < 4; mt++) {
        #pragma unroll
        for (int nt = 0; nt < 4; nt++) {
            int row0 = by*BM + wm*64 + mt*16 + g;
            int col  = bx*BN + wn*32 + nt*8 + 2*q4;
            float2 bb = *(const float2*)(bias + col);
            float2 o0 = make_float2(acc[mt][nt][0] + bb.x, acc[mt][nt][1] + bb.y);
            float2 o1 = make_float2(acc[mt][nt][2] + bb.x, acc[mt][nt][3] + bb.y);
            *(float2*)(C + (size_t)row0*DM + col)     = o0;
            *(float2*)(C + (size_t)(row0+8)*DM + col) = o1;
        }
    }
}

// ---------------------------------------------------------------------------
// TF32 tensor-core flash attention.
// grid (NSEQ/64, NH, 4): z = which*2 + b ; 256 threads = 8 warps.
// Warp grid: wm = warp>>1 (4, rows 16 each), wn = warp&1 (2, cols 32 each).
// Q fragments register-resident. S = Q K^T and O += P V via m16n8k8 mma.
// P reuses the K smem buffer. Softmax: quad shfl + cross-warp smem reduce.
// ---------------------------------------------------------------------------
#define ABR 64
#define ABC 64
__global__ __launch_bounds__(256) void attn_tf32(
    const float* __restrict__ qir,  const float* __restrict__ kvis, const float* __restrict__ vvis,
    const float* __restrict__ qvis, const float* __restrict__ kir,  const float* __restrict__ vir,
    float* __restrict__ att0, float* __restrict__ att1)
{
    __shared__ unsigned KsPs[ABC][68];  // K [key][d] during S ; P [q][key] during PV
    __shared__ unsigned Vs[ABC][68];    // V [key][d]
    __shared__ float redM[2][ABR];
    __shared__ float redS[2][ABR];

    int z = blockIdx.z;
    int which = z >> 1;
    int b = z & 1;
    const float *Qg, *Kg, *Vg; float* Og;
    if (which == 0) { Qg = qir;  Kg = kvis; Vg = vvis; Og = att0; }
    else            { Qg = qvis; Kg = kir;  Vg = vir;  Og = att1; }

    int t    = threadIdx.x;
    int warp = t >> 5, lane = t & 31;
    int g    = lane >> 2;
    int q4   = lane & 3;
    int wm   = warp >> 1;           // 0..3 : q rows [wm*16, +16)
    int wn   = warp & 1;            // 0..1 : cols   [wn*32, +32)
    int R0   = wm*16 + g;
    int R1   = R0 + 8;

    int h    = blockIdx.y;
    int qblk = blockIdx.x;
    const size_t headoff = (size_t)h * DK;
    const size_t batoff  = (size_t)b * NSEQ;

    // ---- Q fragments in registers (scaled, tf32) ----
    unsigned qf[8][4];
    {
        const float* qbase = Qg + (batoff + qblk*ABR)*DM + headoff;
        const float scale = 0.125f;
        #pragma unroll
        for (int kk = 0; kk < 8; kk++) {
            int c = kk*8 + q4;
            qf[kk][0] = f2tf(qbase[(size_t)R0*DM + c]     * scale);
            qf[kk][1] = f2tf(qbase[(size_t)R1*DM + c]     * scale);
            qf[kk][2] = f2tf(qbase[(size_t)R0*DM + c + 4] * scale);
            qf[kk][3] = f2tf(qbase[(size_t)R1*DM + c + 4] * scale);
        }
    }

    float m0 = -INFINITY, m1 = -INFINITY, l0 = 0.f, l1 = 0.f;
    float o[4][4];
    #pragma unroll
    for (int nt = 0; nt < 4; nt++)
        #pragma unroll
        for (int c = 0; c < 4; c++) o[nt][c] = 0.f;

    for (int kt = 0; kt < NSEQ/ABC; kt++) {
        // ---- stage K, V (tf32) ----
        #pragma unroll
        for (int i = 0; i < 4; i++) {
            int idx = t + i*256;           // 0..1023
            int row = idx >> 4;            // key row 0..63
            int d4  = (idx & 15) * 4;      // d col
            size_t goff = (batoff + kt*ABC + row)*DM + headoff + d4;
            float4 kv = *(const float4*)(Kg + goff);
            float4 vv = *(const float4*)(Vg + goff);
            *(uint4*)&KsPs[row][d4] = make_uint4(f2tf(kv.x), f2tf(kv.y), f2tf(kv.z), f2tf(kv.w));
            *(uint4*)&Vs[row][d4]   = make_uint4(f2tf(vv.x), f2tf(vv.y), f2tf(vv.z), f2tf(vv.w));
        }
        __syncthreads();

        // ---- S = Q @ K^T ----
        float s[4][4];
        #pragma unroll
        for (int nt = 0; nt < 4; nt++)
            #pragma unroll
            for (int c = 0; c < 4; c++) s[nt][c] = 0.f;

        #pragma unroll
        for (int kk = 0; kk < 8; kk++) {
            int kc = kk*8 + q4;
            unsigned bf[4][2];
            #pragma unroll
            for (int nt = 0; nt < 4; nt++) {
                int nc = wn*32 + nt*8 + g;
                bf[nt][0] = KsPs[nc][kc];
                bf[nt][1] = KsPs[nc][kc+4];
            }
            #pragma unroll
            for (int nt = 0; nt < 4; nt++)
                mma_tf32(s[nt][0], s[nt][1], s[nt][2], s[nt][3],
                         qf[kk][0], qf[kk][1], qf[kk][2], qf[kk][3],
                         bf[nt][0], bf[nt][1]);
        }

        // ---- row max (quad shfl + cross-warp smem) ----
        float mx0 = -INFINITY, mx1 = -INFINITY;
        #pragma unroll
        for (int nt = 0; nt < 4; nt++) {
            mx0 = fmaxf(mx0, fmaxf(s[nt][0], s[nt][1]));
            mx1 = fmaxf(mx1, fmaxf(s[nt][2], s[nt][3]));
        }
        mx0 = fmaxf(mx0, __shfl_xor_sync(0xffffffffu, mx0, 1));
        mx0 = fmaxf(mx0, __shfl_xor_sync(0xffffffffu, mx0, 2));
        mx1 = fmaxf(mx1, __shfl_xor_sync(0xffffffffu, mx1, 1));
        mx1 = fmaxf(mx1, __shfl_xor_sync(0xffffffffu, mx1, 2));
        if (q4 == 0) { redM[wn][R0] = mx0; redM[wn][R1] = mx1; }
        __syncthreads();

        float nm0 = fmaxf(m0, fmaxf(redM[0][R0], redM[1][R0]));
        float nm1 = fmaxf(m1, fmaxf(redM[0][R1], redM[1][R1]));
        float c0 = __expf(m0 - nm0);
        float c1 = __expf(m1 - nm1);
        m0 = nm0; m1 = nm1;

        float ps0 = 0.f, ps1 = 0.f;
        #pragma unroll
        for (int nt = 0; nt < 4; nt++) {
            s[nt][0] = __expf(s[nt][0] - nm0);
            s[nt][1] = __expf(s[nt][1] - nm0);
            s[nt][2] = __expf(s[nt][2] - nm1);
            s[nt][3] = __expf(s[nt][3] - nm1);
            ps0 += s[nt][0] + s[nt][1];
            ps1 += s[nt][2] + s[nt][3];
        }
        ps0 += __shfl_xor_sync(0xffffffffu, ps0, 1);
        ps0 += __shfl_xor_sync(0xffffffffu, ps0, 2);
        ps1 += __shfl_xor_sync(0xffffffffu, ps1, 1);
        ps1 += __shfl_xor_sync(0xffffffffu, ps1, 2);
        if (q4 == 0) { redS[wn][R0] = ps0; redS[wn][R1] = ps1; }

        // ---- write P into K buffer (K reads finished before redM sync) ----
        #pragma unroll
        for (int nt = 0; nt < 4; nt++) {
            int col = wn*32 + nt*8 + 2*q4;
            *(uint2*)&KsPs[R0][col] = make_uint2(f2tf(s[nt][0]), f2tf(s[nt][1]));
            *(uint2*)&KsPs[R1][col] = make_uint2(f2tf(s[nt][2]), f2tf(s[nt][3]));
        }
        // rescale O
        #pragma unroll
        for (int nt = 0; nt < 4; nt++) {
            o[nt][0] *= c0; o[nt][1] *= c0;
            o[nt][2] *= c1; o[nt][3] *= c1;
        }
        __syncthreads();

        l0 = l0*c0 + redS[0][R0] + redS[1][R0];
        l1 = l1*c1 + redS[0][R1] + redS[1][R1];

        // ---- O += P @ V ----
        #pragma unroll
        for (int kk = 0; kk < 8; kk++) {
            int kc = kk*8 + q4;
            unsigned af[4];
            af[0] = KsPs[R0][kc];
            af[1] = KsPs[R1][kc];
            af[2] = KsPs[R0][kc+4];
            af[3] = KsPs[R1][kc+4];
            #pragma unroll
            for (int nt = 0; nt < 4; nt++) {
                int dc = wn*32 + nt*8 + g;
                unsigned b0 = Vs[kk*8 + q4][dc];
                unsigned b1 = Vs[kk*8 + q4 + 4][dc];
                mma_tf32(o[nt][0], o[nt][1], o[nt][2], o[nt][3],
                         af[0], af[1], af[2], af[3], b0, b1);
            }
        }
        __syncthreads();
    }

    // ---- epilogue ----
    float i0 = 1.0f / l0;
    float i1 = 1.0f / l1;
    #pragma unroll
    for (int nt = 0; nt < 4; nt++) {
        size_t col = headoff + wn*32 + nt*8 + 2*q4;
        float* p0 = Og + (batoff + qblk*ABR + R0)*DM + col;
        float* p1 = Og + (batoff + qblk*ABR + R1)*DM + col;
        *(float2*)p0 = make_float2(o[nt][0]*i0, o[nt][1]*i0);
        *(float2*)p1 = make_float2(o[nt][2]*i1, o[nt][3]*i1);
    }
}

// ---------------------------------------------------------------------------
// Launch
// ---------------------------------------------------------------------------
extern "C" void kernel_launch(void* const* d_in, const int* in_sizes, int n_in,
                              void* d_out, int out_size)
{
    const float* rgb    = (const float*)d_in[0];
    const float* ir     = (const float*)d_in[1];
    const float* ln0_w  = (const float*)d_in[2];
    const float* ln0_b  = (const float*)d_in[3];
    const float* ln1_w  = (const float*)d_in[4];
    const float* ln1_b  = (const float*)d_in[5];
    const float* Wq_vis = (const float*)d_in[6];
    const float* bq_vis = (const float*)d_in[7];
    const float* Wk_vis = (const float*)d_in[8];
    const float* bk_vis = (const float*)d_in[9];
    const float* Wq_ir  = (const float*)d_in[10];
    const float* bq_ir  = (const float*)d_in[11];
    const float* Wk_ir  = (const float*)d_in[12];
    const float* bk_ir  = (const float*)d_in[13];
    const float* Wv_vis = (const float*)d_in[14];
    const float* bv_vis = (const float*)d_in[15];
    const float* Wv_ir  = (const float*)d_in[16];
    const float* bv_ir  = (const float*)d_in[17];
    const float* Wo_vis = (const float*)d_in[18];
    const float* bo_vis = (const float*)d_in[19];
    const float* Wo_ir  = (const float*)d_in[20];
    const float* bo_ir  = (const float*)d_in[21];
    float* out = (float*)d_out;

    float* scr = nullptr;
    cudaGetSymbolAddress((void**)&scr, g_scratch);
    float* rgbn = scr + 0*SLOT;
    float* irn  = scr + 1*SLOT;
    float* qvis = scr + 2*SLOT;
    float* kvis = scr + 3*SLOT;
    float* vvis = scr + 4*SLOT;
    float* qir  = scr + 5*SLOT;
    float* kir  = scr + 6*SLOT;
    float* vir  = scr + 7*SLOT;
    float* att0 = scr + 8*SLOT;
    float* att1 = scr + 9*SLOT;

    // 1. LayerNorms
    ln_kernel<<<2*ROWS, 256>>>(rgb, ir, ln0_w, ln0_b, ln1_w, ln1_b, rgbn, irn);

    // 2. All six projections in one batched launch
    GemmBatch proj;
    proj.A[0]=rgbn; proj.W[0]=Wq_vis; proj.bias[0]=bq_vis; proj.C[0]=qvis;
    proj.A[1]=rgbn; proj.W[1]=Wk_vis; proj.bias[1]=bk_vis; proj.C[1]=kvis;
    proj.A[2]=rgbn; proj.W[2]=Wv_vis; proj.bias[2]=bv_vis; proj.C[2]=vvis;
    proj.A[3]=irn;  proj.W[3]=Wq_ir;  proj.bias[3]=bq_ir;  proj.C[3]=qir;
    proj.A[4]=irn;  proj.W[4]=Wk_ir;  proj.bias[4]=bk_ir;  proj.C[4]=kir;
    proj.A[5]=irn;  proj.W[5]=Wv_ir;  proj.bias[5]=bv_ir;  proj.C[5]=vir;
    dim3 pgrid(DM/BN, ROWS/BM, 6);   // (6, 32, 6)
    gemm_tf32<<<pgrid, 256>>>(proj);

    // 3. Both cross-attentions in one launch
    dim3 agrid(NSEQ/ABR, NH, 4);     // (32, 12, 4)
    attn_tf32<<<agrid, 256>>>(qir, kvis, vvis, qvis, kir, vir, att0, att1);

    // 4. Output projections straight into d_out (out_vis then out_ir)
    GemmBatch op;
    op.A[0]=att0; op.W[0]=Wo_vis; op.bias[0]=bo_vis; op.C[0]=out;
    op.A[1]=att1; op.W[1]=Wo_ir;  op.bias[1]=bo_ir;  op.C[1]=out + SLOT;
    for (int i = 2; i < 6; i++) { op.A[i]=att0; op.W[i]=Wo_vis; op.bias[i]=bo_vis; op.C[i]=out; }
    dim3 ogrid(DM/BN, ROWS/BM, 2);   // (6, 32, 2)
    gemm_tf32<<<ogrid, 256>>>(op);
}